// round 8
// baseline (speedup 1.0000x reference)
#include <cuda_runtime.h>
#include <cuda_fp16.h>
#include <cstdint>

#define NN 100000
#define NE 1600000
#define DD 128
#define SCAN_B 512
#define NSCAN ((NN + SCAN_B - 1) / SCAN_B)

// ---------------- scratch (static device globals) ----------------
__device__ __half g_hn[NN * DD];    // (h @ W) * src_norm  (messages, fp16)
__device__ __half g_h[NN * DD];     // aggregated activations, fp16 (GEMM-A operand)
__device__ __half g_x16[NN * DD];   // fp16 copy of feats
__device__ __half g_w1h[DD * DD];
__device__ __half g_w2h[DD * DD];
__device__ __half g_w3h[DD * DD];
__device__ int    g_cin[NN];
__device__ int    g_cout[NN];
__device__ int    g_fill[NN];
__device__ int    g_off[NN + 1];    // CSR row offsets (by dst)
__device__ int    g_csr[NE];        // src ids sorted by dst
__device__ float  g_srcnorm[NN];
__device__ float  g_dstnorm[NN];
__device__ int    g_bsum[NSCAN];
__device__ int    g_bpre[NSCAN];

// ---------------- CSR build ----------------
__global__ void k_zero(int n) {
    int i = blockIdx.x * blockDim.x + threadIdx.x;
    if (i < n) { g_cin[i] = 0; g_cout[i] = 0; g_fill[i] = 0; }
}

__global__ void k_count(const int* __restrict__ src,
                        const int* __restrict__ dst, int E) {
    int i = blockIdx.x * blockDim.x + threadIdx.x;
    if (i < E) {
        atomicAdd(&g_cout[src[i]], 1);
        atomicAdd(&g_cin[dst[i]], 1);
    }
}

__global__ void k_norm(int n) {
    int i = blockIdx.x * blockDim.x + threadIdx.x;
    if (i < n) {
        g_srcnorm[i] = rsqrtf((float)max(g_cout[i], 1));
        g_dstnorm[i] = rsqrtf((float)max(g_cin[i], 1));
    }
}

__global__ void k_scan1(int n) {
    __shared__ int s[SCAN_B];
    int t = threadIdx.x;
    int g = blockIdx.x * SCAN_B + t;
    int v = (g < n) ? g_cin[g] : 0;
    s[t] = v;
    __syncthreads();
    for (int o = 1; o < SCAN_B; o <<= 1) {
        int x = (t >= o) ? s[t - o] : 0;
        __syncthreads();
        s[t] += x;
        __syncthreads();
    }
    if (g < n) g_off[g] = s[t] - v;
    if (t == SCAN_B - 1) g_bsum[blockIdx.x] = s[t];
}

__global__ void k_scan2(int nb, int n) {
    if (threadIdx.x == 0 && blockIdx.x == 0) {
        int run = 0;
        for (int b = 0; b < nb; b++) { g_bpre[b] = run; run += g_bsum[b]; }
        g_off[n] = run;
    }
}

__global__ void k_scan3(int n) {
    int g = blockIdx.x * blockDim.x + threadIdx.x;
    if (g < n) g_off[g] += g_bpre[g / SCAN_B];
}

__global__ void k_fill(const int* __restrict__ src,
                       const int* __restrict__ dst, int E) {
    int e = blockIdx.x * blockDim.x + threadIdx.x;
    if (e < E) {
        int d = dst[e];
        int p = g_off[d] + atomicAdd(&g_fill[d], 1);
        g_csr[p] = src[e];
    }
}

// ---------------- fp32 -> fp16 converts (once per launch) -------------------
__global__ void k_cvt(const float* __restrict__ in, __half* __restrict__ out, int n4) {
    int i = blockIdx.x * blockDim.x + threadIdx.x;   // over n/4 float4s
    if (i >= n4) return;
    float4 v = ((const float4*)in)[i];
    uint2 p;
    *(__half2*)&p.x = __floats2half2_rn(v.x, v.y);
    *(__half2*)&p.y = __floats2half2_rn(v.z, v.w);
    ((uint2*)out)[i] = p;
}

__global__ void k_cvtW(const float* __restrict__ W1, const float* __restrict__ W2,
                       const float* __restrict__ W3) {
    int i = blockIdx.x * blockDim.x + threadIdx.x;   // 3 * 4096 float4s
    int w = i >> 12, j = i & 4095;
    const float* in = (w == 0) ? W1 : (w == 1) ? W2 : W3;
    __half* out = (w == 0) ? g_w1h : (w == 1) ? g_w2h : g_w3h;
    float4 v = ((const float4*)in)[j];
    uint2 p;
    *(__half2*)&p.x = __floats2half2_rn(v.x, v.y);
    *(__half2*)&p.y = __floats2half2_rn(v.z, v.w);
    ((uint2*)out)[j] = p;
}

// ---------------- GEMM: g_hn = fp16( (A16 @ W16) * src_norm ) ----------------
// HMMA m16n8k16, fp32 accum. Block 128x128, 8 warps (4M x 2N), warp 32x64,
// BK=32, cp.async double-buffered A and W staging (all fp16).
#define APAD 40    // 80B rows, ldmatrix conflict-free, 16B-aligned chunks
#define BPAD 136   // 272B rows

__device__ __forceinline__ void cp16(uint32_t smem, const void* g) {
    asm volatile("cp.async.cg.shared.global [%0], [%1], 16;" :: "r"(smem), "l"(g));
}

__global__ void __launch_bounds__(256)
gemm_kernel(const __half* __restrict__ A, const __half* __restrict__ W16, int M) {
    __shared__ __half As[2][128 * APAD];
    __shared__ __half Bs[2][32 * BPAD];

    const int t    = threadIdx.x;
    const int lane = t & 31;
    const int w    = t >> 5;
    const int wm   = w & 3;
    const int wn   = w >> 2;
    const int row0 = blockIdx.x * 128;

    float d[2][8][4];
#pragma unroll
    for (int mt = 0; mt < 2; mt++)
#pragma unroll
        for (int nt = 0; nt < 8; nt++)
#pragma unroll
            for (int r = 0; r < 4; r++) d[mt][nt][r] = 0.f;

    // issue one BK=32 stage (A: 512 chunks, W: 512 chunks; 2 each per thread)
    auto issue = [&](int kk, int buf) {
#pragma unroll
        for (int i = 0; i < 2; i++) {
            int f = t + i * 256;                 // 0..511
            int row = f >> 2, c = f & 3;         // A: 4x16B chunks per row
            int gr = min(row0 + row, M - 1);     // clamp; epilogue masks stores
            cp16((uint32_t)__cvta_generic_to_shared(&As[buf][row * APAD + c * 8]),
                 &A[(size_t)gr * 128 + kk + c * 8]);
        }
#pragma unroll
        for (int i = 0; i < 2; i++) {
            int f = t + i * 256;
            int k = f >> 4, c = f & 15;          // W: 16x16B chunks per row
            cp16((uint32_t)__cvta_generic_to_shared(&Bs[buf][k * BPAD + c * 8]),
                 &W16[(size_t)(kk + k) * 128 + c * 8]);
        }
        asm volatile("cp.async.commit_group;");
    };

    issue(0, 0);

#pragma unroll
    for (int it = 0; it < 4; it++) {
        if (it < 3) issue((it + 1) * 32, (it + 1) & 1);
        if (it < 3) asm volatile("cp.async.wait_group 1;");
        else        asm volatile("cp.async.wait_group 0;");
        __syncthreads();

        const __half* as = As[it & 1];
        const __half* bs = Bs[it & 1];
#pragma unroll
        for (int ks = 0; ks < 32; ks += 16) {
            unsigned af[2][4];
#pragma unroll
            for (int mt = 0; mt < 2; mt++) {
                int r = wm * 32 + mt * 16 + (lane & 15);
                int kb = ks + ((lane >> 4) << 3);
                unsigned addr = (unsigned)__cvta_generic_to_shared(&as[r * APAD + kb]);
                asm volatile("ldmatrix.sync.aligned.m8n8.x4.shared.b16 {%0,%1,%2,%3}, [%4];"
                             : "=r"(af[mt][0]), "=r"(af[mt][1]),
                               "=r"(af[mt][2]), "=r"(af[mt][3]) : "r"(addr));
            }
            unsigned bf[8][2];
#pragma unroll
            for (int nt = 0; nt < 8; nt++) {
                int krow = ks + (lane & 15);
                int n0 = wn * 64 + nt * 8;
                unsigned addr = (unsigned)__cvta_generic_to_shared(&bs[krow * BPAD + n0]);
                asm volatile("ldmatrix.sync.aligned.m8n8.x2.trans.shared.b16 {%0,%1}, [%2];"
                             : "=r"(bf[nt][0]), "=r"(bf[nt][1]) : "r"(addr));
            }
#pragma unroll
            for (int mt = 0; mt < 2; mt++)
#pragma unroll
                for (int nt = 0; nt < 8; nt++)
                    asm volatile(
                        "mma.sync.aligned.m16n8k16.row.col.f32.f16.f16.f32 "
                        "{%0,%1,%2,%3}, {%4,%5,%6,%7}, {%8,%9}, {%0,%1,%2,%3};"
                        : "+f"(d[mt][nt][0]), "+f"(d[mt][nt][1]),
                          "+f"(d[mt][nt][2]), "+f"(d[mt][nt][3])
                        : "r"(af[mt][0]), "r"(af[mt][1]),
                          "r"(af[mt][2]), "r"(af[mt][3]),
                          "r"(bf[nt][0]), "r"(bf[nt][1]));
        }
        __syncthreads();
    }

    // epilogue: scale rows by src_norm, write fp16 messages
#pragma unroll
    for (int mt = 0; mt < 2; mt++) {
        int gr0 = row0 + wm * 32 + mt * 16 + (lane >> 2);
        int gr1 = gr0 + 8;
        float s0 = (gr0 < M) ? g_srcnorm[gr0] : 0.f;
        float s1 = (gr1 < M) ? g_srcnorm[gr1] : 0.f;
#pragma unroll
        for (int nt = 0; nt < 8; nt++) {
            int gc = wn * 64 + nt * 8 + ((lane & 3) << 1);
            if (gr0 < M)
                *(__half2*)&g_hn[(size_t)gr0 * 128 + gc] =
                    __floats2half2_rn(d[mt][nt][0] * s0, d[mt][nt][1] * s0);
            if (gr1 < M)
                *(__half2*)&g_hn[(size_t)gr1 * 128 + gc] =
                    __floats2half2_rn(d[mt][nt][2] * s1, d[mt][nt][3] * s1);
        }
    }
}

// ---------------- CSR aggregation: one warp per dst node --------------------
// fp16 gather (one LDG.64 per lane), fp32 accumulate.
// FINAL=0: g_h = fp16(relu(acc*dstnorm + bias));  FINAL=1: out fp32, no relu.
template <int FINAL>
__global__ void __launch_bounds__(256)
agg_kernel(const float* __restrict__ bias, float* __restrict__ out, int n) {
    int w = blockIdx.x * 8 + (threadIdx.x >> 5);
    if (w >= n) return;
    int lane = threadIdx.x & 31;

    int start = g_off[w];
    int end   = g_off[w + 1];

    float4 acc = make_float4(0.f, 0.f, 0.f, 0.f);

    for (int i = start; i < end; i += 32) {
        int myid = (i + lane < end) ? g_csr[i + lane] : 0;
        int cnt = min(32, end - i);
#pragma unroll 4
        for (int j = 0; j < cnt; j++) {
            int s = __shfl_sync(0xffffffffu, myid, j);
            uint2 v = *(const uint2*)&g_hn[(size_t)s * 128 + lane * 4];
            float2 a = __half22float2(*(__half2*)&v.x);
            float2 b = __half22float2(*(__half2*)&v.y);
            acc.x += a.x; acc.y += a.y; acc.z += b.x; acc.w += b.y;
        }
    }

    float dn = g_dstnorm[w];
    float4 b = *(const float4*)&bias[lane * 4];
    float4 o = make_float4(fmaf(acc.x, dn, b.x), fmaf(acc.y, dn, b.y),
                           fmaf(acc.z, dn, b.z), fmaf(acc.w, dn, b.w));
    if (FINAL) {
        *(float4*)&out[(size_t)w * 128 + lane * 4] = o;
    } else {
        o.x = fmaxf(o.x, 0.f); o.y = fmaxf(o.y, 0.f);
        o.z = fmaxf(o.z, 0.f); o.w = fmaxf(o.w, 0.f);
        uint2 p;
        *(__half2*)&p.x = __floats2half2_rn(o.x, o.y);
        *(__half2*)&p.y = __floats2half2_rn(o.z, o.w);
        *(uint2*)&g_h[(size_t)w * 128 + lane * 4] = p;
    }
}

// ---------------- launch ----------------
extern "C" void kernel_launch(void* const* d_in, const int* in_sizes, int n_in,
                              void* d_out, int out_size) {
    const float* feats = (const float*)d_in[0];
    const float* W1 = (const float*)d_in[1];
    const float* b1 = (const float*)d_in[2];
    const float* W2 = (const float*)d_in[3];
    const float* b2 = (const float*)d_in[4];
    const float* W3 = (const float*)d_in[5];
    const float* b3 = (const float*)d_in[6];
    const int* src = (const int*)d_in[7];
    const int* dst = (const int*)d_in[8];
    float* out = (float*)d_out;

    const int M = in_sizes[0] / DD;   // 100000
    const int E = in_sizes[7];        // 1600000

    __half *hp = nullptr, *xp = nullptr, *w1p = nullptr, *w2p = nullptr, *w3p = nullptr;
    cudaGetSymbolAddress((void**)&hp, g_h);
    cudaGetSymbolAddress((void**)&xp, g_x16);
    cudaGetSymbolAddress((void**)&w1p, g_w1h);
    cudaGetSymbolAddress((void**)&w2p, g_w2h);
    cudaGetSymbolAddress((void**)&w3p, g_w3h);

    const int nb_node = (M + 255) / 256;
    const int nb_edge = (E + 255) / 256;
    const int nb_gemm = (M + 127) / 128;
    const int nb_agg  = (M + 7) / 8;
    const int nb_vec4 = (M * DD / 4 + 255) / 256;
    const int nscan   = (M + SCAN_B - 1) / SCAN_B;

    // ---- build norms + CSR (by dst) ----
    k_zero<<<nb_node, 256>>>(M);
    k_count<<<nb_edge, 256>>>(src, dst, E);
    k_norm<<<nb_node, 256>>>(M);
    k_scan1<<<nscan, SCAN_B>>>(M);
    k_scan2<<<1, 32>>>(nscan, M);
    k_scan3<<<nb_node, 256>>>(M);
    k_fill<<<nb_edge, 256>>>(src, dst, E);

    // ---- fp16 operand preparation ----
    k_cvt<<<nb_vec4, 256>>>(feats, xp, M * DD / 4);
    k_cvtW<<<(3 * 4096 + 255) / 256, 256>>>(W1, W2, W3);

    // ---- layer 1 ----
    gemm_kernel<<<nb_gemm, 256>>>(xp, w1p, M);
    agg_kernel<0><<<nb_agg, 256>>>(b1, nullptr, M);
    // ---- layer 2 ----
    gemm_kernel<<<nb_gemm, 256>>>(hp, w2p, M);
    agg_kernel<0><<<nb_agg, 256>>>(b2, nullptr, M);
    // ---- layer 3 ----
    gemm_kernel<<<nb_gemm, 256>>>(hp, w3p, M);
    agg_kernel<1><<<nb_agg, 256>>>(b3, out, M);
}

// round 9
// speedup vs baseline: 1.1308x; 1.1308x over previous
#include <cuda_runtime.h>
#include <cuda_fp16.h>
#include <cstdint>

#define NN 100000
#define NE 1600000
#define DD 128
#define SCAN_B 512
#define NSCAN ((NN + SCAN_B - 1) / SCAN_B)

// ---------------- scratch (static device globals) ----------------
__device__ __half g_hn[NN * DD];    // (h @ W) * src_norm  (messages, fp16)
__device__ __half g_h[NN * DD];     // aggregated activations, fp16 (GEMM-A operand)
__device__ int    g_cin[NN];
__device__ int    g_cout[NN];
__device__ int    g_fill[NN];
__device__ int    g_off[NN + 1];    // CSR row offsets (by dst)
__device__ int    g_csr[NE];        // src ids sorted by dst
__device__ float  g_srcnorm[NN];
__device__ float  g_dstnorm[NN];
__device__ int    g_bsum[NSCAN];
__device__ int    g_bpre[NSCAN];

// ---------------- CSR build ----------------
__global__ void k_zero(int n) {
    int i = blockIdx.x * blockDim.x + threadIdx.x;
    if (i < n) { g_cin[i] = 0; g_cout[i] = 0; g_fill[i] = 0; }
}

__global__ void k_count(const int* __restrict__ src,
                        const int* __restrict__ dst, int E) {
    int i = blockIdx.x * blockDim.x + threadIdx.x;
    if (i < E) {
        atomicAdd(&g_cout[src[i]], 1);
        atomicAdd(&g_cin[dst[i]], 1);
    }
}

__global__ void k_norm(int n) {
    int i = blockIdx.x * blockDim.x + threadIdx.x;
    if (i < n) {
        g_srcnorm[i] = rsqrtf((float)max(g_cout[i], 1));
        g_dstnorm[i] = rsqrtf((float)max(g_cin[i], 1));
    }
}

__global__ void k_scan1(int n) {
    __shared__ int s[SCAN_B];
    int t = threadIdx.x;
    int g = blockIdx.x * SCAN_B + t;
    int v = (g < n) ? g_cin[g] : 0;
    s[t] = v;
    __syncthreads();
    for (int o = 1; o < SCAN_B; o <<= 1) {
        int x = (t >= o) ? s[t - o] : 0;
        __syncthreads();
        s[t] += x;
        __syncthreads();
    }
    if (g < n) g_off[g] = s[t] - v;
    if (t == SCAN_B - 1) g_bsum[blockIdx.x] = s[t];
}

__global__ void k_scan2(int nb, int n) {
    if (threadIdx.x == 0 && blockIdx.x == 0) {
        int run = 0;
        for (int b = 0; b < nb; b++) { g_bpre[b] = run; run += g_bsum[b]; }
        g_off[n] = run;
    }
}

__global__ void k_scan3(int n) {
    int g = blockIdx.x * blockDim.x + threadIdx.x;
    if (g < n) g_off[g] += g_bpre[g / SCAN_B];
}

__global__ void k_fill(const int* __restrict__ src,
                       const int* __restrict__ dst, int E) {
    int e = blockIdx.x * blockDim.x + threadIdx.x;
    if (e < E) {
        int d = dst[e];
        int p = g_off[d] + atomicAdd(&g_fill[d], 1);
        g_csr[p] = src[e];
    }
}

// ---------------- GEMM: g_hn = fp16( (fp16(A) @ fp16(W)) * src_norm ) --------
// HMMA mma.sync m16n8k16, fp32 accumulate. Block 128x128, 8 warps (4M x 2N),
// warp tile 32x64, BK=32. A staged from fp32 (layer 1) or fp16 (layers 2-3).
#define APAD 40    // 32 -> 40 halfs (80B rows: ldmatrix bank-conflict-free)
#define BPAD 136   // 128 -> 136 halfs (272B rows: conflict-free, 16B aligned)

template <typename TA>
__global__ void __launch_bounds__(256)
gemm_kernel(const TA* __restrict__ A, const float* __restrict__ W, int M) {
    __shared__ __half As[128 * APAD];   // [row][k]
    __shared__ __half Bs[32 * BPAD];    // [k][n]

    const int t    = threadIdx.x;
    const int lane = t & 31;
    const int w    = t >> 5;
    const int wm   = w & 3;
    const int wn   = w >> 2;
    const int row0 = blockIdx.x * 128;

    float d[2][8][4];
#pragma unroll
    for (int mt = 0; mt < 2; mt++)
#pragma unroll
        for (int nt = 0; nt < 8; nt++)
#pragma unroll
            for (int r = 0; r < 4; r++) d[mt][nt][r] = 0.f;

    for (int kk = 0; kk < 128; kk += 32) {
        // ---- stage A tile (128 x 32) ----
        if constexpr (sizeof(TA) == 4) {
#pragma unroll
            for (int i = 0; i < 4; i++) {
                int f = t + i * 256;
                int row = f >> 3, c4 = f & 7;
                int gr = row0 + row;
                float4 v = (gr < M) ? *(const float4*)&A[(size_t)gr * 128 + kk + c4 * 4]
                                    : make_float4(0.f, 0.f, 0.f, 0.f);
                __half2 h0 = __floats2half2_rn(v.x, v.y);
                __half2 h1 = __floats2half2_rn(v.z, v.w);
                __half2* p = (__half2*)&As[row * APAD + c4 * 4];
                p[0] = h0; p[1] = h1;
            }
        } else {
#pragma unroll
            for (int i = 0; i < 2; i++) {
                int f = t + i * 256;
                int row = f >> 2, c8 = f & 3;
                int gr = row0 + row;
                uint4 v = (gr < M)
                    ? *(const uint4*)&A[(size_t)gr * 128 + kk + c8 * 8]
                    : make_uint4(0u, 0u, 0u, 0u);
                *(uint4*)&As[row * APAD + c8 * 8] = v;
            }
        }
        // ---- stage W tile (32 x 128), fp32 -> fp16 ----
#pragma unroll
        for (int i = 0; i < 4; i++) {
            int f = t + i * 256;
            int k = f >> 5, c4 = f & 31;
            float4 v = *(const float4*)&W[(size_t)(kk + k) * 128 + c4 * 4];
            __half2 h0 = __floats2half2_rn(v.x, v.y);
            __half2 h1 = __floats2half2_rn(v.z, v.w);
            __half2* p = (__half2*)&Bs[k * BPAD + c4 * 4];
            p[0] = h0; p[1] = h1;
        }
        __syncthreads();

#pragma unroll
        for (int ks = 0; ks < 32; ks += 16) {
            unsigned af[2][4];
#pragma unroll
            for (int mt = 0; mt < 2; mt++) {
                int r = wm * 32 + mt * 16 + (lane & 15);
                int kb = ks + ((lane >> 4) << 3);
                unsigned addr = (unsigned)__cvta_generic_to_shared(&As[r * APAD + kb]);
                asm volatile("ldmatrix.sync.aligned.m8n8.x4.shared.b16 {%0,%1,%2,%3}, [%4];"
                             : "=r"(af[mt][0]), "=r"(af[mt][1]),
                               "=r"(af[mt][2]), "=r"(af[mt][3]) : "r"(addr));
            }
            unsigned bf[8][2];
#pragma unroll
            for (int nt = 0; nt < 8; nt++) {
                int krow = ks + (lane & 15);
                int n0 = wn * 64 + nt * 8;
                unsigned addr = (unsigned)__cvta_generic_to_shared(&Bs[krow * BPAD + n0]);
                asm volatile("ldmatrix.sync.aligned.m8n8.x2.trans.shared.b16 {%0,%1}, [%2];"
                             : "=r"(bf[nt][0]), "=r"(bf[nt][1]) : "r"(addr));
            }
#pragma unroll
            for (int mt = 0; mt < 2; mt++)
#pragma unroll
                for (int nt = 0; nt < 8; nt++)
                    asm volatile(
                        "mma.sync.aligned.m16n8k16.row.col.f32.f16.f16.f32 "
                        "{%0,%1,%2,%3}, {%4,%5,%6,%7}, {%8,%9}, {%0,%1,%2,%3};"
                        : "+f"(d[mt][nt][0]), "+f"(d[mt][nt][1]),
                          "+f"(d[mt][nt][2]), "+f"(d[mt][nt][3])
                        : "r"(af[mt][0]), "r"(af[mt][1]),
                          "r"(af[mt][2]), "r"(af[mt][3]),
                          "r"(bf[nt][0]), "r"(bf[nt][1]));
        }
        __syncthreads();
    }

    // epilogue: scale rows by src_norm, write fp16 messages
#pragma unroll
    for (int mt = 0; mt < 2; mt++) {
        int gr0 = row0 + wm * 32 + mt * 16 + (lane >> 2);
        int gr1 = gr0 + 8;
        float s0 = (gr0 < M) ? g_srcnorm[gr0] : 0.f;
        float s1 = (gr1 < M) ? g_srcnorm[gr1] : 0.f;
#pragma unroll
        for (int nt = 0; nt < 8; nt++) {
            int gc = wn * 64 + nt * 8 + ((lane & 3) << 1);
            if (gr0 < M)
                *(__half2*)&g_hn[(size_t)gr0 * 128 + gc] =
                    __floats2half2_rn(d[mt][nt][0] * s0, d[mt][nt][1] * s0);
            if (gr1 < M)
                *(__half2*)&g_hn[(size_t)gr1 * 128 + gc] =
                    __floats2half2_rn(d[mt][nt][2] * s1, d[mt][nt][3] * s1);
        }
    }
}

// ---------------- CSR aggregation: one warp per dst node --------------------
// fp16 gather (one LDG.64 per lane), fp32 accumulate.
// FINAL=0: g_h = fp16(relu(acc*dstnorm + bias));  FINAL=1: out fp32, no relu.
template <int FINAL>
__global__ void __launch_bounds__(256)
agg_kernel(const float* __restrict__ bias, float* __restrict__ out, int n) {
    int w = blockIdx.x * 8 + (threadIdx.x >> 5);
    if (w >= n) return;
    int lane = threadIdx.x & 31;

    int start = g_off[w];
    int end   = g_off[w + 1];

    float4 acc = make_float4(0.f, 0.f, 0.f, 0.f);

    for (int i = start; i < end; i += 32) {
        int myid = (i + lane < end) ? g_csr[i + lane] : 0;
        int cnt = min(32, end - i);
#pragma unroll 4
        for (int j = 0; j < cnt; j++) {
            int s = __shfl_sync(0xffffffffu, myid, j);
            uint2 v = *(const uint2*)&g_hn[(size_t)s * 128 + lane * 4];
            float2 a = __half22float2(*(__half2*)&v.x);
            float2 b = __half22float2(*(__half2*)&v.y);
            acc.x += a.x; acc.y += a.y; acc.z += b.x; acc.w += b.y;
        }
    }

    float dn = g_dstnorm[w];
    float4 b = *(const float4*)&bias[lane * 4];
    float4 o = make_float4(fmaf(acc.x, dn, b.x), fmaf(acc.y, dn, b.y),
                           fmaf(acc.z, dn, b.z), fmaf(acc.w, dn, b.w));
    if (FINAL) {
        *(float4*)&out[(size_t)w * 128 + lane * 4] = o;
    } else {
        o.x = fmaxf(o.x, 0.f); o.y = fmaxf(o.y, 0.f);
        o.z = fmaxf(o.z, 0.f); o.w = fmaxf(o.w, 0.f);
        uint2 p;
        *(__half2*)&p.x = __floats2half2_rn(o.x, o.y);
        *(__half2*)&p.y = __floats2half2_rn(o.z, o.w);
        *(uint2*)&g_h[(size_t)w * 128 + lane * 4] = p;
    }
}

// ---------------- launch ----------------
extern "C" void kernel_launch(void* const* d_in, const int* in_sizes, int n_in,
                              void* d_out, int out_size) {
    const float* feats = (const float*)d_in[0];
    const float* W1 = (const float*)d_in[1];
    const float* b1 = (const float*)d_in[2];
    const float* W2 = (const float*)d_in[3];
    const float* b2 = (const float*)d_in[4];
    const float* W3 = (const float*)d_in[5];
    const float* b3 = (const float*)d_in[6];
    const int* src = (const int*)d_in[7];
    const int* dst = (const int*)d_in[8];
    float* out = (float*)d_out;

    const int M = in_sizes[0] / DD;   // 100000
    const int E = in_sizes[7];        // 1600000

    __half* hp = nullptr;
    cudaGetSymbolAddress((void**)&hp, g_h);

    const int nb_node = (M + 255) / 256;
    const int nb_edge = (E + 255) / 256;
    const int nb_gemm = (M + 127) / 128;
    const int nb_agg  = (M + 7) / 8;
    const int nscan   = (M + SCAN_B - 1) / SCAN_B;

    // Fork/join: CSR scan+fill (depends only on k_count) runs concurrently
    // with k_norm + layer-1 GEMM on the main stream. Streams/events are
    // created per call and intentionally not destroyed (kernel_launch runs
    // only a handful of times; destroying during graph capture risks
    // invalidating the capture). No device memory is allocated.
    cudaStream_t s2;
    cudaEvent_t evA, evB;
    cudaStreamCreateWithFlags(&s2, cudaStreamNonBlocking);
    cudaEventCreateWithFlags(&evA, cudaEventDisableTiming);
    cudaEventCreateWithFlags(&evB, cudaEventDisableTiming);

    // ---- degrees (common root) ----
    k_zero<<<nb_node, 256>>>(M);
    k_count<<<nb_edge, 256>>>(src, dst, E);
    cudaEventRecord(evA, 0);

    // ---- side stream: CSR offsets + fill ----
    cudaStreamWaitEvent(s2, evA, 0);
    k_scan1<<<nscan, SCAN_B, 0, s2>>>(M);
    k_scan2<<<1, 32, 0, s2>>>(nscan, M);
    k_scan3<<<nb_node, 256, 0, s2>>>(M);
    k_fill<<<nb_edge, 256, 0, s2>>>(src, dst, E);
    cudaEventRecord(evB, s2);

    // ---- main stream: norms + layer-1 GEMM (independent of CSR) ----
    k_norm<<<nb_node, 256>>>(M);
    gemm_kernel<float><<<nb_gemm, 256>>>(feats, W1, M);

    // ---- join: aggregation needs the CSR ----
    cudaStreamWaitEvent(0, evB, 0);

    agg_kernel<0><<<nb_agg, 256>>>(b1, nullptr, M);
    // ---- layer 2 ----
    gemm_kernel<__half><<<nb_gemm, 256>>>(hp, W2, M);
    agg_kernel<0><<<nb_agg, 256>>>(b2, nullptr, M);
    // ---- layer 3 ----
    gemm_kernel<__half><<<nb_gemm, 256>>>(hp, W3, M);
    agg_kernel<1><<<nb_agg, 256>>>(b3, out, M);
}